// round 17
// baseline (speedup 1.0000x reference)
#include <cuda_runtime.h>
#include <cuda_fp16.h>
#include <cuda_bf16.h>
#include <math.h>
#include <stdint.h>

#define NN  50000
#define TT  8
#define EE  800000
#define FIN 9
#define HH  64
#define CAP 96
#define TILE_M 128
#define NBLK ((NN + TILE_M - 1) / TILE_M)

__device__ int      g_deg [TT * NN];                 // zeroed by LSTM tail each launch
__device__ int      g_bkt [(size_t)TT * NN * CAP];   // uint4-unit offsets: (t*NN+s)*8
__device__ float    g_dinv[TT * NN];
__device__ uint32_t g_w2p [64 * 32];                 // W2 packed f16 pairs [j][kp]
__device__ uint4    g_hsh [TT * NN * 8];   // layer-1 hs (dinv-scaled), f16
__device__ uint4    g_acth[TT * NN * 8];   // layer-1 activation
__device__ uint4    g_hs2h[TT * NN * 8];   // layer-2 hs
__device__ uint4    g_seqh[TT * NN * 8];   // seq (f16)

// ---------------- MUFU-based nonlinearities --------------------------------
__device__ __forceinline__ float tanh_mufu(float x) {
    float y;
    asm("tanh.approx.f32 %0, %1;" : "=f"(y) : "f"(x));
    return y;
}
__device__ __forceinline__ float sig_mufu(float x) {
    return fmaf(tanh_mufu(x * 0.5f), 0.5f, 0.5f);
}

__device__ __forceinline__ uint32_t packh(float e0, float e1) {
    __half2 p = __floats2half2_rn(e0, e1);
    return *reinterpret_cast<uint32_t*>(&p);
}
__device__ __forceinline__ float2 h2f(uint32_t u) {
    return __half22float2(*reinterpret_cast<__half2*>(&u));
}
__device__ __forceinline__ uint32_t hadd2u(uint32_t a, uint32_t b) {
    __half2 r = __hadd2(*reinterpret_cast<__half2*>(&a), *reinterpret_cast<__half2*>(&b));
    return *reinterpret_cast<uint32_t*>(&r);
}
__device__ __forceinline__ uint4 hadd4(uint4 a, uint4 b) {
    uint4 r;
    r.x = hadd2u(a.x, b.x); r.y = hadd2u(a.y, b.y);
    r.z = hadd2u(a.z, b.z); r.w = hadd2u(a.w, b.w);
    return r;
}
__device__ __forceinline__ void mma_f16(float* d, const uint32_t* a,
                                        uint32_t b0, uint32_t b1) {
    asm volatile(
        "mma.sync.aligned.m16n8k16.row.col.f32.f16.f16.f32 "
        "{%0,%1,%2,%3}, {%4,%5,%6,%7}, {%8,%9}, {%0,%1,%2,%3};"
        : "+f"(d[0]), "+f"(d[1]), "+f"(d[2]), "+f"(d[3])
        : "r"(a[0]), "r"(a[1]), "r"(a[2]), "r"(a[3]), "r"(b0), "r"(b1));
}

// 2 edges per thread, int2 vector loads
__global__ void k_fill_bucket(const int* __restrict__ ei) {
    int idx = blockIdx.x * blockDim.x + threadIdx.x;
    if (idx >= TT * EE / 2) return;
    int t = idx / (EE / 2), e2 = (idx - t * (EE / 2)) * 2;
    const int* base = ei + (size_t)t * 2 * EE;
    int2 sp = *reinterpret_cast<const int2*>(base + e2);
    int2 dp = *reinterpret_cast<const int2*>(base + EE + e2);
    int tNN = t * NN;
    int td0 = tNN + dp.x;
    int p0 = atomicAdd(&g_deg[td0], 1);
    g_bkt[(size_t)td0 * CAP + p0] = (tNN + sp.x) * 8;
    int td1 = tNN + dp.y;
    int p1 = atomicAdd(&g_deg[td1], 1);
    g_bkt[(size_t)td1 * CAP + p1] = (tNN + sp.y) * 8;
}

// pre-pack W2 into [j][kp] f16-pair layout with coalesced reads
__global__ void k_packw2(const float* __restrict__ W2) {
    int t = blockIdx.x * blockDim.x + threadIdx.x;
    if (t >= 2048) return;
    int j = t & 63, kp = t >> 6;
    float e0 = W2[(2 * kp) * 64 + j];
    float e1 = W2[(2 * kp + 1) * 64 + j];
    g_w2p[j * 32 + kp] = packh(e0, e1);
}

// layer-1 GEMM (K=9): coalesced x staging; dinv; -> g_hsh
__global__ __launch_bounds__(128) void k_gemm1h(
    const float* __restrict__ x, const float* __restrict__ W1)
{
    __shared__ float sW[FIN * HH];
    __shared__ float sX[128 * FIN];
    int tid = threadIdx.x;
    for (int i = tid; i < FIN * HH; i += 128) sW[i] = W1[i];
    int base = blockIdx.x * 128;
#pragma unroll
    for (int i = 0; i < FIN; i++) {
        int idx = tid + i * 128;
        sX[idx] = x[(size_t)base * FIN + idx];
    }
    __syncthreads();
    int n = base + tid;
    if (n >= TT * NN) return;
    float dv = rsqrtf((float)(g_deg[n] + 1));
    g_dinv[n] = dv;
    float xv[FIN];
#pragma unroll
    for (int k = 0; k < FIN; k++) xv[k] = sX[tid * FIN + k];
#pragma unroll
    for (int c = 0; c < HH; c += 8) {
        float o[8];
#pragma unroll
        for (int j = 0; j < 8; j++) o[j] = 0.f;
#pragma unroll
        for (int k = 0; k < FIN; k++) {
            float xk = xv[k];
#pragma unroll
            for (int j = 0; j < 8; j++)
                o[j] = fmaf(xk, sW[k * HH + c + j], o[j]);
        }
        uint4 u;
        u.x = packh(o[0] * dv, o[1] * dv);
        u.y = packh(o[2] * dv, o[3] * dv);
        u.z = packh(o[4] * dv, o[5] * dv);
        u.w = packh(o[6] * dv, o[7] * dv);
        g_hsh[(size_t)n * 8 + c / 8] = u;
    }
}

// ---------- gather: FOUR nodes per warp, two-level fp16 tree ---------------
__device__ __forceinline__ void acc8(float* f, uint4 p) {
    float2 q0 = h2f(p.x), q1 = h2f(p.y), q2 = h2f(p.z), q3 = h2f(p.w);
    f[0] += q0.x; f[1] += q0.y; f[2] += q1.x; f[3] += q1.y;
    f[4] += q2.x; f[5] += q2.y; f[6] += q3.x; f[7] += q3.y;
}

__device__ __forceinline__ void gather4n(const uint4* __restrict__ src,
                                         const int* __restrict__ bkt,
                                         int deg, int gw, int l8, float* f) {
    uint4 s = src[(size_t)gw * 8 + l8];
    float2 a0 = h2f(s.x), a1 = h2f(s.y), a2 = h2f(s.z), a3 = h2f(s.w);
    f[0] = a0.x; f[1] = a0.y; f[2] = a1.x; f[3] = a1.y;
    f[4] = a2.x; f[5] = a2.y; f[6] = a3.x; f[7] = a3.y;
    int e = 0;
    for (; e + 7 < deg; e += 8) {
        int4 oa = *reinterpret_cast<const int4*>(bkt + e);
        int4 ob = *reinterpret_cast<const int4*>(bkt + e + 4);
        uint4 v0 = src[oa.x + l8], v1 = src[oa.y + l8];
        uint4 v2 = src[oa.z + l8], v3 = src[oa.w + l8];
        uint4 v4 = src[ob.x + l8], v5 = src[ob.y + l8];
        uint4 v6 = src[ob.z + l8], v7 = src[ob.w + l8];
        uint4 p0 = hadd4(v0, v1), p1 = hadd4(v2, v3);
        uint4 p2 = hadd4(v4, v5), p3 = hadd4(v6, v7);
        uint4 q0 = hadd4(p0, p1), q1 = hadd4(p2, p3);   // sums of 4 (fp16)
        acc8(f, q0); acc8(f, q1);
    }
    if (e + 3 < deg) {
        int4 oa = *reinterpret_cast<const int4*>(bkt + e);
        uint4 v0 = src[oa.x + l8], v1 = src[oa.y + l8];
        uint4 v2 = src[oa.z + l8], v3 = src[oa.w + l8];
        uint4 p0 = hadd4(v0, v1), p1 = hadd4(v2, v3);
        uint4 q0 = hadd4(p0, p1);
        acc8(f, q0);
        e += 4;
    }
    for (; e < deg; e++) {
        uint4 v = src[bkt[e] + l8];
        acc8(f, v);
    }
}

// layer-1 aggregation -> g_acth
__global__ void k_agg1h(const float* __restrict__ b1) {
    int gw = ((blockIdx.x * blockDim.x + threadIdx.x) >> 3);
    int l8 = threadIdx.x & 7;
    if (gw >= TT * NN) return;
    int deg = g_deg[gw];
    const int* bkt = g_bkt + (size_t)gw * CAP;
    float f[8];
    gather4n(g_hsh, bkt, deg, gw, l8, f);
    float dv = g_dinv[gw];
    float4 bA = *reinterpret_cast<const float4*>(b1 + l8 * 8);
    float4 bB = *reinterpret_cast<const float4*>(b1 + l8 * 8 + 4);
    float a0 = fmaxf(fmaf(f[0], dv, bA.x), 0.f);
    float a1 = fmaxf(fmaf(f[1], dv, bA.y), 0.f);
    float a2 = fmaxf(fmaf(f[2], dv, bA.z), 0.f);
    float a3 = fmaxf(fmaf(f[3], dv, bA.w), 0.f);
    float a4 = fmaxf(fmaf(f[4], dv, bB.x), 0.f);
    float a5 = fmaxf(fmaf(f[5], dv, bB.y), 0.f);
    float a6 = fmaxf(fmaf(f[6], dv, bB.z), 0.f);
    float a7 = fmaxf(fmaf(f[7], dv, bB.w), 0.f);
    uint4 u;
    u.x = packh(a0, a1); u.y = packh(a2, a3);
    u.z = packh(a4, a5); u.w = packh(a6, a7);
    g_acth[(size_t)gw * 8 + l8] = u;
}

// layer-2 GEMM: A = g_acth (exact fp16) @ W2 (pre-packed f16) * dinv -> g_hs2h
#define G2_A   0          // 128 x 36 u32
#define G2_B   4608       // 64 x 36 u32
#define G2_TOT 6912

__global__ __launch_bounds__(512) void k_gemm64h() {
    extern __shared__ uint32_t sg[];
    int tid = threadIdx.x, lane = tid & 31, w = tid >> 5;
    int grp = lane >> 2, tig = lane & 3;
    int wm = w >> 3, wn = w & 7;
    int row0 = blockIdx.x * 128;

#pragma unroll
    for (int i = 0; i < 4; i++) {
        int idx = tid + i * 512;
        int j = idx >> 5, kp = idx & 31;
        sg[G2_B + j * 36 + kp] = g_w2p[idx];
    }
#pragma unroll
    for (int i = 0; i < 2; i++) {
        int idx = tid + i * 512;
        int r = idx >> 3, k4 = idx & 7;
        uint4 v = g_acth[(size_t)(row0 + r) * 8 + k4];
        *reinterpret_cast<uint4*>(&sg[G2_A + r * 36 + 4 * k4]) = v;
    }
    __syncthreads();

    float acc4[4][4] = {};
#pragma unroll
    for (int cs = 0; cs < 4; cs++) {
        int kb = cs * 8;
        int pb = (wn * 8 + grp) * 36 + kb;
        uint32_t b0 = sg[G2_B + pb + tig], b1 = sg[G2_B + pb + tig + 4];
#pragma unroll
        for (int mi = 0; mi < 4; mi++) {
            int rb = wm * 64 + mi * 16;
            uint32_t Ah[4];
            Ah[0] = sg[G2_A + (rb + grp) * 36 + kb + tig];
            Ah[1] = sg[G2_A + (rb + grp + 8) * 36 + kb + tig];
            Ah[2] = sg[G2_A + (rb + grp) * 36 + kb + tig + 4];
            Ah[3] = sg[G2_A + (rb + grp + 8) * 36 + kb + tig + 4];
            mma_f16(acc4[mi], Ah, b0, b1);
        }
    }
#pragma unroll
    for (int mi = 0; mi < 4; mi++) {
#pragma unroll
        for (int rh = 0; rh < 2; rh++) {
            int row = row0 + wm * 64 + mi * 16 + grp + rh * 8;
            float dv = g_dinv[row];
            reinterpret_cast<uint32_t*>(g_hs2h)[(size_t)row * 32 + wn * 4 + tig] =
                packh(acc4[mi][rh * 2] * dv, acc4[mi][rh * 2 + 1] * dv);
        }
    }
}

// layer-2 aggregation -> g_seqh
__global__ void k_agg2h(const float* __restrict__ b) {
    int gw = ((blockIdx.x * blockDim.x + threadIdx.x) >> 3);
    int l8 = threadIdx.x & 7;
    if (gw >= TT * NN) return;
    int deg = g_deg[gw];
    const int* bkt = g_bkt + (size_t)gw * CAP;
    float f[8];
    gather4n(g_hs2h, bkt, deg, gw, l8, f);
    float dv = g_dinv[gw];
    float4 bA = *reinterpret_cast<const float4*>(b + l8 * 8);
    float4 bB = *reinterpret_cast<const float4*>(b + l8 * 8 + 4);
    float a0 = fmaxf(fmaf(f[0], dv, bA.x), 0.f);
    float a1 = fmaxf(fmaf(f[1], dv, bA.y), 0.f);
    float a2 = fmaxf(fmaf(f[2], dv, bA.z), 0.f);
    float a3 = fmaxf(fmaf(f[3], dv, bA.w), 0.f);
    float a4 = fmaxf(fmaf(f[4], dv, bB.x), 0.f);
    float a5 = fmaxf(fmaf(f[5], dv, bB.y), 0.f);
    float a6 = fmaxf(fmaf(f[6], dv, bB.z), 0.f);
    float a7 = fmaxf(fmaf(f[7], dv, bB.w), 0.f);
    uint4 u;
    u.x = packh(a0, a1); u.y = packh(a2, a3);
    u.z = packh(a4, a5); u.w = packh(a6, a7);
    g_seqh[(size_t)gw * 8 + l8] = u;
}

// ====== fused LSTM over all T + head; zeros g_deg at tail ==================
#define L_X    0
#define L_H    4608
#define L_B    9216
#define L_BIAS 26624
#define L_LOG  26880
#define L_TOT  27008

__global__ __launch_bounds__(512, 1) void k_lstm_f16(
    const float* __restrict__ w_ih, const float* __restrict__ w_hh,
    const float* __restrict__ b_ih, const float* __restrict__ b_hh,
    const float* __restrict__ head_w, const float* __restrict__ head_b,
    float* __restrict__ out)
{
    extern __shared__ uint32_t sm_u[];
    float* sBias = reinterpret_cast<float*>(sm_u + L_BIAS);
    float* sLog  = reinterpret_cast<float*>(sm_u + L_LOG);

    int tid = threadIdx.x, lane = tid & 31, w = tid >> 5;
    int grp = lane >> 2, tig = lane & 3;
    int wm = w >> 3, wn = w & 7;
    int row0 = blockIdx.x * TILE_M;
    int j0 = (wn << 3) + tig, j1 = j0 + 4;

    for (int i = tid; i < 256 * 64; i += 512) {
        int p = i >> 6, kp = i & 63;
        int wnp = p >> 5, rem = p & 31, q = rem >> 3, e = rem & 7;
        int gate = ((q & 1) << 1) | (e & 1);
        int L = (gate << 6) + (wnp << 3) + ((q >> 1) << 2) + (e >> 1);
        int k = kp * 2;
        float2 v = (k < 64)
            ? *reinterpret_cast<const float2*>(w_ih + (size_t)L * 64 + k)
            : *reinterpret_cast<const float2*>(w_hh + (size_t)L * 64 + (k - 64));
        sm_u[L_B + p * 68 + kp] = packh(v.x, v.y);
    }
    for (int i = tid; i < 4608; i += 512) sm_u[L_H + i] = 0u;
    if (tid < 256) sBias[tid] = b_ih[tid] + b_hh[tid];
    if (tid < 128) sLog[tid] = 0.f;
#pragma unroll
    for (int i = 0; i < 2; i++) {
        int idx = tid + i * 512;
        int r = idx >> 3, c4 = idx & 7;
        int row = row0 + r;
        uint4 v = make_uint4(0u, 0u, 0u, 0u);
        if (row < NN) v = g_seqh[(size_t)row * 8 + c4];
        *reinterpret_cast<uint4*>(&sm_u[L_X + r * 36 + 4 * c4]) = v;
    }
    float hw0 = head_w[j0], hw1 = head_w[j1];
    float creg[4][2][2];
#pragma unroll
    for (int a = 0; a < 4; a++)
#pragma unroll
        for (int b = 0; b < 2; b++) { creg[a][b][0] = 0.f; creg[a][b][1] = 0.f; }
    __syncthreads();

    for (int t = 0; t < TT; t++) {
        float acc[4][4][4] = {};
#pragma unroll 1
        for (int cs = 0; cs < 8; cs++) {
            const uint32_t* Ap = sm_u + ((cs < 4) ? L_X : L_H);
            int kb = (cs & 3) * 8;
            int kb2 = cs * 8;
            uint32_t Bh[4][2];
#pragma unroll
            for (int q = 0; q < 4; q++) {
                int pb = ((wn << 5) + (q << 3) + grp) * 68 + kb2;
                Bh[q][0] = sm_u[L_B + pb + tig];
                Bh[q][1] = sm_u[L_B + pb + tig + 4];
            }
#pragma unroll
            for (int mi = 0; mi < 4; mi++) {
                int rb = wm * 64 + mi * 16;
                uint32_t Ah[4];
                Ah[0] = Ap[(rb + grp) * 36 + kb + tig];
                Ah[1] = Ap[(rb + grp + 8) * 36 + kb + tig];
                Ah[2] = Ap[(rb + grp) * 36 + kb + tig + 4];
                Ah[3] = Ap[(rb + grp + 8) * 36 + kb + tig + 4];
#pragma unroll
                for (int q = 0; q < 4; q++)
                    mma_f16(acc[mi][q], Ah, Bh[q][0], Bh[q][1]);
            }
        }
        __syncthreads();

        uint4 rx4[2];
        if (t < TT - 1) {
            const uint4* ps = g_seqh + (size_t)(t + 1) * NN * 8;
#pragma unroll
            for (int i = 0; i < 2; i++) {
                int idx = tid + i * 512;
                int r = idx >> 3, c4 = idx & 7;
                int row = row0 + r;
                rx4[i] = (row < NN) ? ps[(size_t)row * 8 + c4]
                                    : make_uint4(0u, 0u, 0u, 0u);
            }
        }

        float bi0 = sBias[j0], bf0_ = sBias[64 + j0], bg0 = sBias[128 + j0], bo0 = sBias[192 + j0];
        float bi1 = sBias[j1], bf1_ = sBias[64 + j1], bg1 = sBias[128 + j1], bo1 = sBias[192 + j1];
#pragma unroll
        for (int mi = 0; mi < 4; mi++) {
#pragma unroll
            for (int rh = 0; rh < 2; rh++) {
                int r = wm * 64 + mi * 16 + grp + rh * 8;
                int ci = rh * 2;
                float gi0 = acc[mi][0][ci] + bi0, gf0 = acc[mi][0][ci + 1] + bf0_;
                float gg0 = acc[mi][1][ci] + bg0, go0 = acc[mi][1][ci + 1] + bo0;
                float gi1 = acc[mi][2][ci] + bi1, gf1 = acc[mi][2][ci + 1] + bf1_;
                float gg1 = acc[mi][3][ci] + bg1, go1 = acc[mi][3][ci + 1] + bo1;
                float c0 = creg[mi][rh][0], c1 = creg[mi][rh][1];
                c0 = sig_mufu(gf0) * c0 + sig_mufu(gi0) * tanh_mufu(gg0);
                c1 = sig_mufu(gf1) * c1 + sig_mufu(gi1) * tanh_mufu(gg1);
                creg[mi][rh][0] = c0; creg[mi][rh][1] = c1;
                float h0 = sig_mufu(go0) * tanh_mufu(c0);
                float h1 = sig_mufu(go1) * tanh_mufu(c1);
                if (t < TT - 1) {
                    int base0 = L_H + r * 36 + (j0 >> 1);
                    int sl = j0 & 1;
                    reinterpret_cast<__half*>(&sm_u[base0])[sl] = __float2half(h0);
                    reinterpret_cast<__half*>(&sm_u[base0 + 2])[sl] = __float2half(h1);
                } else {
                    float v = h0 * hw0 + h1 * hw1;
                    v += __shfl_xor_sync(0xffffffffu, v, 1);
                    v += __shfl_xor_sync(0xffffffffu, v, 2);
                    if (tig == 0) atomicAdd(&sLog[r], v);
                }
            }
        }

        if (t < TT - 1) {
#pragma unroll
            for (int i = 0; i < 2; i++) {
                int idx = tid + i * 512;
                int r = idx >> 3, c4 = idx & 7;
                *reinterpret_cast<uint4*>(&sm_u[L_X + r * 36 + 4 * c4]) = rx4[i];
            }
        }
        __syncthreads();
    }

    if (tid < 128) {
        int row = row0 + tid;
        if (row < NN) out[row] = sLog[tid] + head_b[0];
    }

    // zero g_deg for the next graph replay
    int z0 = blockIdx.x * 1024 + tid;
    if (z0 < TT * NN) g_deg[z0] = 0;
    if (z0 + 512 < TT * NN) g_deg[z0 + 512] = 0;
}

extern "C" void kernel_launch(void* const* d_in, const int* in_sizes, int n_in,
                              void* d_out, int out_size) {
    const float* xs  = (const float*)d_in[0];
    const int*   ei  = (const int*)  d_in[1];
    const float* W1  = (const float*)d_in[2];
    const float* b1  = (const float*)d_in[3];
    const float* W2  = (const float*)d_in[4];
    const float* b2  = (const float*)d_in[5];
    const float* wih = (const float*)d_in[6];
    const float* whh = (const float*)d_in[7];
    const float* bih = (const float*)d_in[8];
    const float* bhh = (const float*)d_in[9];
    const float* hw  = (const float*)d_in[10];
    const float* hb  = (const float*)d_in[11];
    float* out = (float*)d_out;

    cudaFuncSetAttribute(k_lstm_f16,
                         cudaFuncAttributeMaxDynamicSharedMemorySize, L_TOT * 4);
    cudaFuncSetAttribute(k_gemm64h,
                         cudaFuncAttributeMaxDynamicSharedMemorySize, G2_TOT * 4);

    k_fill_bucket<<<(TT * EE / 2 + 255) / 256, 256>>>(ei);
    k_packw2<<<8, 256>>>(W2);

    k_gemm1h<<<(TT * NN + 127) / 128, 128>>>(xs, W1);
    k_agg1h<<<((size_t)TT * NN * 8 + 511) / 512, 512>>>(b1);
    k_gemm64h<<<(TT * NN) / 128, 512, G2_TOT * 4>>>();
    k_agg2h<<<((size_t)TT * NN * 8 + 511) / 512, 512>>>(b2);

    k_lstm_f16<<<NBLK, 512, L_TOT * 4>>>(wih, whh, bih, bhh, hw, hb, out);
}